// round 16
// baseline (speedup 1.0000x reference)
#include <cuda_runtime.h>
#include <cuda_fp16.h>
#include <cstdint>

#define BSZ   128
#define HID   1024
#define TSEQ  372
#define NCTA  128
#define NKT16 66
#define SB_U32 (NKT16 * 4 * 32 * 4)     // 33792 u32 = 135168 B

__device__ uint32_t g_hh[2][65536];      // h hi fragments (fp16x2)
__device__ uint32_t g_hl[2][65536];      // h lo*2048 fragments
__device__ uint32_t g_xh[TSEQ * 2048];   // x hi fragments (2 ktiles)
__device__ uint32_t g_xl[TSEQ * 2048];   // x lo*2048 fragments
__device__ float    g_bias[4096 * BSZ];
__device__ float    g_temb[HID * BSZ];
__device__ float    g_hm[512 * BSZ];
__device__ float    g_part[NCTA * 8 * BSZ];
__device__ unsigned g_cnt8[8 * 32];      // 8 counters, 128B apart

__device__ __forceinline__ float sigm(float x) { return 1.f / (1.f + expf(-x)); }

__device__ __forceinline__ uint32_t pk_h2(float loE, float hiE) {
    uint32_t r;
    asm("cvt.rn.f16x2.f32 %0, %1, %2;" : "=r"(r) : "f"(hiE), "f"(loE));
    return r;
}
__device__ __forceinline__ void split16(float v, float& hi, float& lo) {
    __half h = __float2half_rn(v);
    hi = __half2float(h);
    lo = (v - hi) * 2048.0f;
}
__device__ __forceinline__ void mma16816(float& d0, float& d1, float& d2, float& d3,
                                         uint32_t a0, uint32_t a1, uint32_t a2, uint32_t a3,
                                         uint32_t b0, uint32_t b1) {
    asm("mma.sync.aligned.m16n8k16.row.col.f32.f16.f16.f32 "
        "{%0,%1,%2,%3}, {%4,%5,%6,%7}, {%8,%9}, {%0,%1,%2,%3};"
        : "+f"(d0), "+f"(d1), "+f"(d2), "+f"(d3)
        : "r"(a0), "r"(a1), "r"(a2), "r"(a3), "r"(b0), "r"(b1));
}

// ---------------- setup ----------------
__global__ void s_emb_hm(const float* __restrict__ tval, const float* __restrict__ freqs,
                         const float* __restrict__ phases, const float* __restrict__ W1,
                         const float* __restrict__ b1)
{
    __shared__ float emb[256];
    const int b = blockIdx.x, tid = threadIdx.x;
    const float tv = tval[b];
    emb[tid] = cosf(fmaf(tv, freqs[tid], phases[tid])) * 1.41421356237309515f;
    __syncthreads();
    const float4* e4 = (const float4*)emb;
    for (int u = tid; u < 512; u += 256) {
        const float4* w4 = (const float4*)(W1 + u * 256);
        float s = b1[u];
        #pragma unroll 8
        for (int q = 0; q < 64; ++q) {
            float4 w = w4[q], e = e4[q];
            s += w.x * e.x + w.y * e.y + w.z * e.z + w.w * e.w;
        }
        g_hm[u * BSZ + b] = s * sigm(s);
    }
}

__global__ void s_temb(const float* __restrict__ W2, const float* __restrict__ b2)
{
    __shared__ float sW2[8 * 512];
    const int blk = blockIdx.x, tid = threadIdx.x;
    const int h0 = blk * 8;
    for (int idx = tid; idx < 4096; idx += 128) sW2[idx] = W2[h0 * 512 + idx];
    __syncthreads();
    const int b = tid;
    float acc[8];
    #pragma unroll
    for (int r = 0; r < 8; ++r) acc[r] = b2[h0 + r];
    #pragma unroll 8
    for (int u = 0; u < 512; ++u) {
        const float hmv = g_hm[u * BSZ + b];
        #pragma unroll
        for (int r = 0; r < 8; ++r) acc[r] = fmaf(sW2[r * 512 + u], hmv, acc[r]);
    }
    #pragma unroll
    for (int r = 0; r < 8; ++r) g_temb[(h0 + r) * BSZ + b] = acc[r];
}

__global__ void s_biasx(const float* __restrict__ static_attr, const float* __restrict__ W_ih,
                        const float* __restrict__ b_ih, const float* __restrict__ b_hh,
                        const float* __restrict__ x_past, const float* __restrict__ x_future,
                        const float* __restrict__ noisy)
{
    const int blk = blockIdx.x, tid = threadIdx.x;
    if (blk < 32) {
        __shared__ float sst[27 * 128];
        __shared__ float sw[128 * 27];
        const int r0 = blk * 128;
        for (int idx = tid; idx < 27 * 128; idx += 256) {
            const int k = idx >> 7, b = idx & 127;
            sst[idx] = static_attr[b * 27 + k];
        }
        for (int idx = tid; idx < 128 * 27; idx += 256) {
            const int rl = idx / 27, k = idx - rl * 27;
            sw[idx] = W_ih[(r0 + rl) * 60 + 33 + k];
        }
        __syncthreads();
        for (int o = tid; o < 128 * 128; o += 256) {
            const int rl = o >> 7, b = o & 127;
            const int r = r0 + rl;
            float s = b_ih[r] + b_hh[r];
            #pragma unroll
            for (int k = 0; k < 27; ++k) s = fmaf(sw[rl * 27 + k], sst[k * 128 + b], s);
            g_bias[r * BSZ + b] = s;
        }
        for (int i = tid; i < 2048; i += 256) {
            g_hh[0][blk * 2048 + i] = 0u;
            g_hl[0][blk * 2048 + i] = 0u;
        }
        if (blk == 0 && tid < 8 * 32) g_cnt8[tid] = 0u;
    } else {
        const int t = blk - 32;
        if (tid >= 128) return;
        const int b = tid;
        const int mt = b >> 4, r = b & 15;
        const int gp = r & 7, up = r >> 3;
        const float* src = (t < 365) ? (x_past + (b * 365 + t) * 32)
                                     : (x_future + (b * 7 + (t - 365)) * 32);
        float xv[32];
        const float4* s4 = (const float4*)src;
        #pragma unroll
        for (int q = 0; q < 8; ++q) {
            float4 v = s4[q];
            xv[q * 4 + 0] = v.x; xv[q * 4 + 1] = v.y;
            xv[q * 4 + 2] = v.z; xv[q * 4 + 3] = v.w;
        }
        uint32_t* xh = g_xh + t * 2048;
        uint32_t* xl = g_xl + t * 2048;
        #pragma unroll
        for (int kt = 0; kt < 2; ++kt) {
            #pragma unroll
            for (int tg = 0; tg < 4; ++tg) {
                const int base = ((kt * 8 + mt) * 32 + gp * 4 + tg) * 4;
                #pragma unroll
                for (int hk = 0; hk < 2; ++hk) {
                    const int k0 = kt * 16 + tg * 2 + hk * 8;
                    float h0, l0, h1, l1;
                    split16(xv[k0], h0, l0);
                    split16(xv[k0 + 1], h1, l1);
                    xh[base + up + hk * 2] = pk_h2(h0, h1);
                    xl[base + up + hk * 2] = pk_h2(l0, l1);
                }
            }
        }
    }
}

// 12 MMAs for one mtile slot MT
#define MMA_BLK(MT, Ah_, Al_, B_)                                                  \
    _Pragma("unroll")                                                              \
    for (int nt = 0; nt < 4; ++nt)                                                 \
        mma16816(accM[MT][nt][0], accM[MT][nt][1], accM[MT][nt][2], accM[MT][nt][3],\
                 (Ah_).x, (Ah_).y, (Ah_).z, (Ah_).w, (B_)[nt].x, (B_)[nt].y);      \
    _Pragma("unroll")                                                              \
    for (int nt = 0; nt < 4; ++nt)                                                 \
        mma16816(accC[MT][nt][0], accC[MT][nt][1], accC[MT][nt][2], accC[MT][nt][3],\
                 (Al_).x, (Al_).y, (Al_).z, (Al_).w, (B_)[nt].x, (B_)[nt].y);      \
    _Pragma("unroll")                                                              \
    for (int nt = 0; nt < 4; ++nt)                                                 \
        mma16816(accC[MT][nt][0], accC[MT][nt][1], accC[MT][nt][2], accC[MT][nt][3],\
                 (Ah_).x, (Ah_).y, (Ah_).z, (Ah_).w, (B_)[nt].z, (B_)[nt].w);

// ---------------- main LSTM (fp16-split mma.sync, 512 thr, 4-way K-split, 2 mtiles/warp) ----------------
__global__ void __launch_bounds__(512, 1)
lstm_main(const float* __restrict__ W_hh, const float* __restrict__ W_ih,
          const float* __restrict__ Wh, const float* __restrict__ noisy)
{
    extern __shared__ __align__(16) uint32_t sm[];
    uint32_t* sB   = sm;                      // [66][4][32][4] u32
    float* bias_s  = (float*)(sm + SB_U32);   // 4096
    float* temb_s  = bias_s + 4096;           // 1024
    float* wh_s    = temb_s + 1024;           // 32 (8 used)
    float* red     = wh_s + 32;               // 4 owners x 128 x 25 floats

    const int tid = threadIdx.x;
    const int w   = tid >> 5, lane = tid & 31;
    const int mw  = w & 3, kg = w >> 2;        // 4 M-warps x 4 K-groups
    const int g   = lane >> 2, tig = lane & 3;
    const int cta = blockIdx.x;
    const int j0  = cta * 8;

    // weights into SMEM fragments (kt 0..63 = W_hh, 64..65 = W_ih k0..31)
    for (int idx = tid; idx < NKT16 * 4 * 32; idx += 512) {
        const int ln = idx & 31, nt = (idx >> 5) & 3, kt = idx >> 7;
        const int n = nt * 8 + (ln >> 2);
        const int tg = ln & 3;
        const int r = (n >> 3) * HID + j0 + (n & 7);
        const int k0 = kt * 16 + tg * 2;
        float wv[4];
        #pragma unroll
        for (int q = 0; q < 4; ++q) {
            const int k = k0 + (q >> 1) * 8 + (q & 1);
            float v = (k < 1024) ? W_hh[r * 1024 + k] : W_ih[r * 60 + (k - 1024)];
            wv[q] = v * 256.0f;
        }
        float h0, l0, h1, l1, h2, l2, h3, l3;
        split16(wv[0], h0, l0); split16(wv[1], h1, l1);
        split16(wv[2], h2, l2); split16(wv[3], h3, l3);
        uint32_t* dst = sB + idx * 4;
        dst[0] = pk_h2(h0, h1);
        dst[1] = pk_h2(h2, h3);
        dst[2] = pk_h2(l0, l1);
        dst[3] = pk_h2(l2, l3);
    }
    for (int idx = tid; idx < 32 * 128; idx += 512) {
        const int n = idx >> 7, b = idx & 127;
        bias_s[idx] = g_bias[((n >> 3) * HID + j0 + (n & 7)) * BSZ + b];
    }
    for (int idx = tid; idx < 8 * 128; idx += 512) {
        const int jl = idx >> 7, b = idx & 127;
        temb_s[idx] = g_temb[(j0 + jl) * BSZ + b];
    }
    if (tid < 8) wh_s[tid] = Wh[j0 + tid];
    __syncthreads();

    const int mt0  = mw * 2;                  // this warp's mtiles: mt0, mt0+1
    const int ktw  = cta >> 1;
    const int regw = (cta & 1) * 2;
    const int kt0h = kg * 16;                 // 16 h-ktiles per K-group
    const int mwlane = mw * 32 + lane;
    // epilogue ownership: kg -> (mtile-slot kg>>1, batch-half kg&1)
    const int emt = kg >> 1, ehalf = kg & 1;
    const int bb  = (mt0 + emt) * 16 + g + ehalf * 8;
    const int jl0 = 2 * tig, jl1 = jl0 + 1;
    float cst[2] = {0.f, 0.f};

    const uint4* sB4 = (const uint4*)sB;

    for (int t = 0; t < TSEQ; ++t) {
        const uint4* hh4 = (const uint4*)(g_hh[t & 1]);
        const uint4* hl4 = (const uint4*)(g_hl[t & 1]);

        float accM[2][4][4], accC[2][4][4];
        #pragma unroll
        for (int mt = 0; mt < 2; ++mt)
            #pragma unroll
            for (int nt = 0; nt < 4; ++nt)
                #pragma unroll
                for (int e = 0; e < 4; ++e) { accM[mt][nt][e] = 0.f; accC[mt][nt][e] = 0.f; }

        uint4 rh[2][2], rl[2][2];
        // slot0 = first h tile (both mtiles)
        #pragma unroll
        for (int mt = 0; mt < 2; ++mt) {
            const int off = (kt0h * 8 + mt0 + mt) * 32 + lane;
            rh[0][mt] = __ldcg(hh4 + off);
            rl[0][mt] = __ldcg(hl4 + off);
        }

        // ---- peeled x-tile for kg 0/1 (B tile 64+kg, A from g_xh[kg]) ----
        if (kg < 2) {
            uint4 axh[2], axl[2];
            #pragma unroll
            for (int mt = 0; mt < 2; ++mt) {
                const int off = (kg * 8 + mt0 + mt) * 32 + lane;
                axh[mt] = __ldcg((const uint4*)(g_xh + t * 2048) + off);
                axl[mt] = __ldcg((const uint4*)(g_xl + t * 2048) + off);
            }
            uint4 Bv[4];
            #pragma unroll
            for (int nt = 0; nt < 4; ++nt)
                Bv[nt] = sB4[((64 + kg) * 4 + nt) * 32 + lane];
            MMA_BLK(0, axh[0], axl[0], Bv)
            MMA_BLK(1, axh[1], axl[1], Bv)
        }

        // ---- main loop: 16 h tiles, unroll 2, ring slot k&1 ----
        #pragma unroll 2
        for (int k = 0; k < 16; ++k) {
            const int cur = k & 1, nxt = cur ^ 1;
            if (k + 1 < 16) {
                #pragma unroll
                for (int mt = 0; mt < 2; ++mt) {
                    const int off = ((kt0h + k + 1) * 8 + mt0 + mt) * 32 + lane;
                    rh[nxt][mt] = __ldcg(hh4 + off);
                    rl[nxt][mt] = __ldcg(hl4 + off);
                }
            }
            uint4 Bv[4];
            #pragma unroll
            for (int nt = 0; nt < 4; ++nt)
                Bv[nt] = sB4[((kt0h + k) * 4 + nt) * 32 + lane];
            MMA_BLK(0, rh[cur][0], rl[cur][0], Bv)
            MMA_BLK(1, rh[cur][1], rl[cur][1], Bv)
        }

        // combine hi/lo into accM (becomes 'part')
        #pragma unroll
        for (int mt = 0; mt < 2; ++mt)
            #pragma unroll
            for (int nt = 0; nt < 4; ++nt)
                #pragma unroll
                for (int e = 0; e < 4; ++e)
                    accM[mt][nt][e] += accC[mt][nt][e] * 4.8828125e-4f;

        // ship partials to each owner (o != kg); owner o covers (mt o>>1, e-pair (o&1)*2)
        #pragma unroll
        for (int o = 0; o < 4; ++o) {
            if (o == kg) continue;
            const int c = kg - (kg > o ? 1 : 0);
            const int omt = o >> 1, oep = (o & 1) * 2;
            float* dst = red + o * 3200 + mwlane * 25 + c * 8;
            #pragma unroll
            for (int nt = 0; nt < 4; ++nt) {
                dst[nt * 2 + 0] = accM[omt][nt][oep + 0];
                dst[nt * 2 + 1] = accM[omt][nt][oep + 1];
            }
        }
        __syncthreads();

        // sum own + 3 contributions
        float sum[4][2];
        {
            const int oep = ehalf * 2;
            #pragma unroll
            for (int nt = 0; nt < 4; ++nt) {
                sum[nt][0] = accM[emt][nt][oep + 0];
                sum[nt][1] = accM[emt][nt][oep + 1];
            }
            #pragma unroll
            for (int c = 0; c < 3; ++c) {
                const float* src = red + kg * 3200 + mwlane * 25 + c * 8;
                #pragma unroll
                for (int nt = 0; nt < 4; ++nt) {
                    sum[nt][0] += src[nt * 2 + 0];
                    sum[nt][1] += src[nt * 2 + 1];
                }
            }
        }

        // epilogue: this thread owns batch bb, hidden jl0/jl1
        float fl = 0.f;
        if (t >= 364) fl = __ldcg(noisy + bb * 8 + (t - 364));
        float hv[2];
        #pragma unroll
        for (int ee = 0; ee < 2; ++ee) {
            const int jl = ee ? jl1 : jl0;
            float gi = sum[0][ee] * 0.00390625f + bias_s[(0 + jl) * 128 + bb];
            float gf = sum[1][ee] * 0.00390625f + bias_s[(8 + jl) * 128 + bb];
            float gg = sum[2][ee] * 0.00390625f + bias_s[(16 + jl) * 128 + bb];
            float go = sum[3][ee] * 0.00390625f + bias_s[(24 + jl) * 128 + bb];
            if (t >= 364) {
                gi += fl * __ldcg(W_ih + (j0 + jl) * 60 + 32);
                gf += fl * __ldcg(W_ih + (1024 + j0 + jl) * 60 + 32);
                gg += fl * __ldcg(W_ih + (2048 + j0 + jl) * 60 + 32);
                go += fl * __ldcg(W_ih + (3072 + j0 + jl) * 60 + 32);
            }
            cst[ee] = sigm(gf) * cst[ee] + sigm(gi) * tanhf(gg);
            float hn = sigm(go) * tanhf(cst[ee]);
            if (t == 363) {
                const float te = temb_s[jl * 128 + bb];
                hn += te; cst[ee] += te;
            }
            hv[ee] = hn;
        }

        // store h (one fp16x2 word per thread) in fragment layout
        {
            float h0, l0, h1, l1;
            split16(hv[0], h0, l0); split16(hv[1], h1, l1);
            const int addr = ((ktw * 8 + mt0 + emt) * 32 + g * 4 + tig) * 4 + regw + ehalf;
            g_hh[(t + 1) & 1][addr] = pk_h2(h0, h1);
            g_hl[(t + 1) & 1][addr] = pk_h2(l0, l1);
        }

        if (t >= 364) {
            float p = hv[0] * wh_s[jl0] + hv[1] * wh_s[jl1];
            p += __shfl_xor_sync(0xFFFFFFFFu, p, 1);
            p += __shfl_xor_sync(0xFFFFFFFFu, p, 2);
            if (tig == 0)
                g_part[(cta * 8 + (t - 364)) * BSZ + bb] = p;
        }

        // ---- grid barrier: release-arrive on 8 spread counters + acquire poll ----
        __syncthreads();
        if (tid == 0)
            asm volatile("red.release.gpu.global.add.u32 [%0], 1;"
                         :: "l"(g_cnt8 + (cta & 7) * 32) : "memory");
        if (tid < 8) {
            const unsigned target = 16u * (unsigned)(t + 1);
            unsigned v;
            do {
                asm volatile("ld.acquire.gpu.global.u32 %0, [%1];"
                             : "=r"(v) : "l"(g_cnt8 + tid * 32) : "memory");
                if (v < target) __nanosleep(32);
            } while (v < target);
        }
        __syncthreads();
    }
}

__global__ void out_kernel(const float* __restrict__ bh, float* __restrict__ out)
{
    const int idx = blockIdx.x * blockDim.x + threadIdx.x;
    if (idx >= BSZ * 8) return;
    const int b = idx >> 3, tf = idx & 7;
    float s = bh[0];
    #pragma unroll 4
    for (int c = 0; c < NCTA; ++c)
        s += g_part[(c * 8 + tf) * BSZ + b];
    out[idx] = s;
}

extern "C" void kernel_launch(void* const* d_in, const int* in_sizes, int n_in,
                              void* d_out, int out_size)
{
    const int smemb = SB_U32 * 4 + (4096 + 1024 + 32 + 4 * 3200) * 4;
    cudaFuncSetAttribute(lstm_main, cudaFuncAttributeMaxDynamicSharedMemorySize, smemb);
    s_emb_hm<<<128, 256>>>((const float*)d_in[2], (const float*)d_in[9],
                           (const float*)d_in[10], (const float*)d_in[11],
                           (const float*)d_in[12]);
    s_temb<<<128, 128>>>((const float*)d_in[13], (const float*)d_in[14]);
    s_biasx<<<404, 256>>>((const float*)d_in[4], (const float*)d_in[5],
                          (const float*)d_in[7], (const float*)d_in[8],
                          (const float*)d_in[0], (const float*)d_in[3],
                          (const float*)d_in[1]);
    lstm_main<<<NCTA, 512, smemb>>>((const float*)d_in[6], (const float*)d_in[5],
                                    (const float*)d_in[15], (const float*)d_in[1]);
    out_kernel<<<(BSZ * 8 + 255) / 256, 256>>>((const float*)d_in[16], (float*)d_out);
}

// round 17
// speedup vs baseline: 1.1022x; 1.1022x over previous
#include <cuda_runtime.h>
#include <cuda_fp16.h>
#include <cstdint>

#define BSZ   128
#define HID   1024
#define TSEQ  372
#define NCTA  128
#define NKT16 66
#define SB_U32 (NKT16 * 4 * 32 * 4)     // 33792 u32 = 135168 B

__device__ uint32_t g_hh[2][65536];      // h hi fragments (fp16x2)
__device__ uint32_t g_hl[2][65536];      // h lo*2048 fragments
__device__ uint32_t g_xh[TSEQ * 2048];   // x hi fragments (2 ktiles)
__device__ uint32_t g_xl[TSEQ * 2048];   // x lo*2048 fragments
__device__ float    g_bias[4096 * BSZ];
__device__ float    g_temb[HID * BSZ];
__device__ float    g_hm[512 * BSZ];
__device__ float    g_part[NCTA * 8 * BSZ];
__device__ unsigned g_cnt8[8 * 32];      // 8 counters, 128B apart

__device__ __forceinline__ float sigm(float x) { return 1.f / (1.f + expf(-x)); }

__device__ __forceinline__ uint32_t pk_h2(float loE, float hiE) {
    uint32_t r;
    asm("cvt.rn.f16x2.f32 %0, %1, %2;" : "=r"(r) : "f"(hiE), "f"(loE));
    return r;
}
__device__ __forceinline__ void split16(float v, float& hi, float& lo) {
    __half h = __float2half_rn(v);
    hi = __half2float(h);
    lo = (v - hi) * 2048.0f;
}
__device__ __forceinline__ void mma16816(float& d0, float& d1, float& d2, float& d3,
                                         uint32_t a0, uint32_t a1, uint32_t a2, uint32_t a3,
                                         uint32_t b0, uint32_t b1) {
    asm("mma.sync.aligned.m16n8k16.row.col.f32.f16.f16.f32 "
        "{%0,%1,%2,%3}, {%4,%5,%6,%7}, {%8,%9}, {%0,%1,%2,%3};"
        : "+f"(d0), "+f"(d1), "+f"(d2), "+f"(d3)
        : "r"(a0), "r"(a1), "r"(a2), "r"(a3), "r"(b0), "r"(b1));
}

// ---------------- setup ----------------
__global__ void s_emb_hm(const float* __restrict__ tval, const float* __restrict__ freqs,
                         const float* __restrict__ phases, const float* __restrict__ W1,
                         const float* __restrict__ b1)
{
    __shared__ float emb[256];
    const int b = blockIdx.x, tid = threadIdx.x;
    const float tv = tval[b];
    emb[tid] = cosf(fmaf(tv, freqs[tid], phases[tid])) * 1.41421356237309515f;
    __syncthreads();
    const float4* e4 = (const float4*)emb;
    for (int u = tid; u < 512; u += 256) {
        const float4* w4 = (const float4*)(W1 + u * 256);
        float s = b1[u];
        #pragma unroll 8
        for (int q = 0; q < 64; ++q) {
            float4 w = w4[q], e = e4[q];
            s += w.x * e.x + w.y * e.y + w.z * e.z + w.w * e.w;
        }
        g_hm[u * BSZ + b] = s * sigm(s);
    }
}

__global__ void s_temb(const float* __restrict__ W2, const float* __restrict__ b2)
{
    __shared__ float sW2[8 * 512];
    const int blk = blockIdx.x, tid = threadIdx.x;
    const int h0 = blk * 8;
    for (int idx = tid; idx < 4096; idx += 128) sW2[idx] = W2[h0 * 512 + idx];
    __syncthreads();
    const int b = tid;
    float acc[8];
    #pragma unroll
    for (int r = 0; r < 8; ++r) acc[r] = b2[h0 + r];
    #pragma unroll 8
    for (int u = 0; u < 512; ++u) {
        const float hmv = g_hm[u * BSZ + b];
        #pragma unroll
        for (int r = 0; r < 8; ++r) acc[r] = fmaf(sW2[r * 512 + u], hmv, acc[r]);
    }
    #pragma unroll
    for (int r = 0; r < 8; ++r) g_temb[(h0 + r) * BSZ + b] = acc[r];
}

__global__ void s_biasx(const float* __restrict__ static_attr, const float* __restrict__ W_ih,
                        const float* __restrict__ b_ih, const float* __restrict__ b_hh,
                        const float* __restrict__ x_past, const float* __restrict__ x_future,
                        const float* __restrict__ noisy)
{
    const int blk = blockIdx.x, tid = threadIdx.x;
    if (blk < 32) {
        __shared__ float sst[27 * 128];
        __shared__ float sw[128 * 27];
        const int r0 = blk * 128;
        for (int idx = tid; idx < 27 * 128; idx += 256) {
            const int k = idx >> 7, b = idx & 127;
            sst[idx] = static_attr[b * 27 + k];
        }
        for (int idx = tid; idx < 128 * 27; idx += 256) {
            const int rl = idx / 27, k = idx - rl * 27;
            sw[idx] = W_ih[(r0 + rl) * 60 + 33 + k];
        }
        __syncthreads();
        for (int o = tid; o < 128 * 128; o += 256) {
            const int rl = o >> 7, b = o & 127;
            const int r = r0 + rl;
            float s = b_ih[r] + b_hh[r];
            #pragma unroll
            for (int k = 0; k < 27; ++k) s = fmaf(sw[rl * 27 + k], sst[k * 128 + b], s);
            g_bias[r * BSZ + b] = s;
        }
        for (int i = tid; i < 2048; i += 256) {
            g_hh[0][blk * 2048 + i] = 0u;
            g_hl[0][blk * 2048 + i] = 0u;
        }
        if (blk == 0 && tid < 8 * 32) g_cnt8[tid] = 0u;
    } else {
        const int t = blk - 32;
        if (tid >= 128) return;
        const int b = tid;
        const int mt = b >> 4, r = b & 15;
        const int gp = r & 7, up = r >> 3;
        const float* src = (t < 365) ? (x_past + (b * 365 + t) * 32)
                                     : (x_future + (b * 7 + (t - 365)) * 32);
        float xv[32];
        const float4* s4 = (const float4*)src;
        #pragma unroll
        for (int q = 0; q < 8; ++q) {
            float4 v = s4[q];
            xv[q * 4 + 0] = v.x; xv[q * 4 + 1] = v.y;
            xv[q * 4 + 2] = v.z; xv[q * 4 + 3] = v.w;
        }
        uint32_t* xh = g_xh + t * 2048;
        uint32_t* xl = g_xl + t * 2048;
        #pragma unroll
        for (int kt = 0; kt < 2; ++kt) {
            #pragma unroll
            for (int tg = 0; tg < 4; ++tg) {
                const int base = ((kt * 8 + mt) * 32 + gp * 4 + tg) * 4;
                #pragma unroll
                for (int hk = 0; hk < 2; ++hk) {
                    const int k0 = kt * 16 + tg * 2 + hk * 8;
                    float h0, l0, h1, l1;
                    split16(xv[k0], h0, l0);
                    split16(xv[k0 + 1], h1, l1);
                    xh[base + up + hk * 2] = pk_h2(h0, h1);
                    xl[base + up + hk * 2] = pk_h2(l0, l1);
                }
            }
        }
    }
}

// 6 MMAs: one nt, both mtiles (Ah/Al indexed by mt)
#define MMA_NT(NT, B_)                                                             \
    _Pragma("unroll")                                                              \
    for (int mt = 0; mt < 2; ++mt) {                                               \
        mma16816(accM[mt][NT][0], accM[mt][NT][1], accM[mt][NT][2], accM[mt][NT][3],\
                 Ah[mt].x, Ah[mt].y, Ah[mt].z, Ah[mt].w, (B_).x, (B_).y);          \
        mma16816(accC[mt][NT][0], accC[mt][NT][1], accC[mt][NT][2], accC[mt][NT][3],\
                 Al[mt].x, Al[mt].y, Al[mt].z, Al[mt].w, (B_).x, (B_).y);          \
        mma16816(accC[mt][NT][0], accC[mt][NT][1], accC[mt][NT][2], accC[mt][NT][3],\
                 Ah[mt].x, Ah[mt].y, Ah[mt].z, Ah[mt].w, (B_).z, (B_).w);          \
    }

// ---------------- main LSTM (fp16-split mma.sync, 512 thr, 4-way K-split, 2 mtiles/warp) ----------------
__global__ void __launch_bounds__(512, 1)
lstm_main(const float* __restrict__ W_hh, const float* __restrict__ W_ih,
          const float* __restrict__ Wh, const float* __restrict__ noisy)
{
    extern __shared__ __align__(16) uint32_t sm[];
    uint32_t* sB   = sm;                      // [66][4][32][4] u32
    float* bias_s  = (float*)(sm + SB_U32);   // 4096
    float* temb_s  = bias_s + 4096;           // 1024
    float* wh_s    = temb_s + 1024;           // 32 (8 used)
    float* red     = wh_s + 32;               // 4 owners x 128 x 25 floats

    const int tid = threadIdx.x;
    const int w   = tid >> 5, lane = tid & 31;
    const int mw  = w & 3, kg = w >> 2;        // 4 M-warps x 4 K-groups
    const int g   = lane >> 2, tig = lane & 3;
    const int cta = blockIdx.x;
    const int j0  = cta * 8;

    for (int idx = tid; idx < NKT16 * 4 * 32; idx += 512) {
        const int ln = idx & 31, nt = (idx >> 5) & 3, kt = idx >> 7;
        const int n = nt * 8 + (ln >> 2);
        const int tg = ln & 3;
        const int r = (n >> 3) * HID + j0 + (n & 7);
        const int k0 = kt * 16 + tg * 2;
        float wv[4];
        #pragma unroll
        for (int q = 0; q < 4; ++q) {
            const int k = k0 + (q >> 1) * 8 + (q & 1);
            float v = (k < 1024) ? W_hh[r * 1024 + k] : W_ih[r * 60 + (k - 1024)];
            wv[q] = v * 256.0f;
        }
        float h0, l0, h1, l1, h2, l2, h3, l3;
        split16(wv[0], h0, l0); split16(wv[1], h1, l1);
        split16(wv[2], h2, l2); split16(wv[3], h3, l3);
        uint32_t* dst = sB + idx * 4;
        dst[0] = pk_h2(h0, h1);
        dst[1] = pk_h2(h2, h3);
        dst[2] = pk_h2(l0, l1);
        dst[3] = pk_h2(l2, l3);
    }
    for (int idx = tid; idx < 32 * 128; idx += 512) {
        const int n = idx >> 7, b = idx & 127;
        bias_s[idx] = g_bias[((n >> 3) * HID + j0 + (n & 7)) * BSZ + b];
    }
    for (int idx = tid; idx < 8 * 128; idx += 512) {
        const int jl = idx >> 7, b = idx & 127;
        temb_s[idx] = g_temb[(j0 + jl) * BSZ + b];
    }
    if (tid < 8) wh_s[tid] = Wh[j0 + tid];
    __syncthreads();

    const int mt0  = mw * 2;
    const int ktw  = cta >> 1;
    const int regw = (cta & 1) * 2;
    const int kt0h = kg * 16;
    const int mwlane = mw * 32 + lane;
    const int emt = kg >> 1, ehalf = kg & 1;
    const int bb  = (mt0 + emt) * 16 + g + ehalf * 8;
    const int jl0 = 2 * tig, jl1 = jl0 + 1;
    float cst[2] = {0.f, 0.f};

    const uint4* sB4 = (const uint4*)sB;
    // loop-invariant base pointers
    const uint4* sBk = sB4 + (kt0h * 4) * 32 + lane;      // B for this K-group
    const uint4* sBx = sB4 + ((64 + kg) * 4) * 32 + lane; // x B-tile (kg<2)

    for (int t = 0; t < TSEQ; ++t) {
        const uint4* hh4 = (const uint4*)(g_hh[t & 1]) + (kt0h * 8 + mt0) * 32 + lane;
        const uint4* hl4 = (const uint4*)(g_hl[t & 1]) + (kt0h * 8 + mt0) * 32 + lane;

        float accM[2][4][4], accC[2][4][4];
        #pragma unroll
        for (int mt = 0; mt < 2; ++mt)
            #pragma unroll
            for (int nt = 0; nt < 4; ++nt)
                #pragma unroll
                for (int e = 0; e < 4; ++e) { accM[mt][nt][e] = 0.f; accC[mt][nt][e] = 0.f; }

        uint4 rh[2][2], rl[2][2];
        #pragma unroll
        for (int mt = 0; mt < 2; ++mt) {
            rh[0][mt] = __ldcg(hh4 + mt * 32);
            rl[0][mt] = __ldcg(hl4 + mt * 32);
        }

        // ---- peeled x-tile for kg 0/1 ----
        if (kg < 2) {
            uint4 Ah[2], Al[2];
            const uint4* xh4 = (const uint4*)(g_xh + t * 2048) + (kg * 8 + mt0) * 32 + lane;
            const uint4* xl4 = (const uint4*)(g_xl + t * 2048) + (kg * 8 + mt0) * 32 + lane;
            #pragma unroll
            for (int mt = 0; mt < 2; ++mt) {
                Ah[mt] = __ldcg(xh4 + mt * 32);
                Al[mt] = __ldcg(xl4 + mt * 32);
            }
            uint4 B0 = sBx[0], B1 = sBx[32];
            MMA_NT(0, B0)
            MMA_NT(1, B1)
            B0 = sBx[64]; B1 = sBx[96];
            MMA_NT(2, B0)
            MMA_NT(3, B1)
        }

        // ---- main loop: 16 h tiles, unroll 2, ring slot k&1 ----
        #pragma unroll 2
        for (int k = 0; k < 16; ++k) {
            const int cur = k & 1, nxt = cur ^ 1;
            if (k + 1 < 16) {
                #pragma unroll
                for (int mt = 0; mt < 2; ++mt) {
                    rh[nxt][mt] = __ldcg(hh4 + (k + 1) * 256 + mt * 32);
                    rl[nxt][mt] = __ldcg(hl4 + (k + 1) * 256 + mt * 32);
                }
            }
            const uint4 Ah[2] = {rh[cur][0], rh[cur][1]};
            const uint4 Al[2] = {rl[cur][0], rl[cur][1]};
            const uint4* Bp = sBk + k * 128;
            uint4 B0 = Bp[0], B1 = Bp[32];
            MMA_NT(0, B0)
            MMA_NT(1, B1)
            B0 = Bp[64]; B1 = Bp[96];
            MMA_NT(2, B0)
            MMA_NT(3, B1)
        }

        // combine hi/lo into accM
        #pragma unroll
        for (int mt = 0; mt < 2; ++mt)
            #pragma unroll
            for (int nt = 0; nt < 4; ++nt)
                #pragma unroll
                for (int e = 0; e < 4; ++e)
                    accM[mt][nt][e] += accC[mt][nt][e] * 4.8828125e-4f;

        // ship partials to each owner (o != kg)
        #pragma unroll
        for (int o = 0; o < 4; ++o) {
            if (o == kg) continue;
            const int c = kg - (kg > o ? 1 : 0);
            const int omt = o >> 1, oep = (o & 1) * 2;
            float* dst = red + o * 3200 + mwlane * 25 + c * 8;
            #pragma unroll
            for (int nt = 0; nt < 4; ++nt) {
                dst[nt * 2 + 0] = accM[omt][nt][oep + 0];
                dst[nt * 2 + 1] = accM[omt][nt][oep + 1];
            }
        }
        __syncthreads();

        // sum own + 3 contributions
        float sum[4][2];
        {
            const int oep = ehalf * 2;
            #pragma unroll
            for (int nt = 0; nt < 4; ++nt) {
                sum[nt][0] = accM[emt][nt][oep + 0];
                sum[nt][1] = accM[emt][nt][oep + 1];
            }
            #pragma unroll
            for (int c = 0; c < 3; ++c) {
                const float* src = red + kg * 3200 + mwlane * 25 + c * 8;
                #pragma unroll
                for (int nt = 0; nt < 4; ++nt) {
                    sum[nt][0] += src[nt * 2 + 0];
                    sum[nt][1] += src[nt * 2 + 1];
                }
            }
        }

        // epilogue
        float fl = 0.f;
        if (t >= 364) fl = __ldcg(noisy + bb * 8 + (t - 364));
        float hv[2];
        #pragma unroll
        for (int ee = 0; ee < 2; ++ee) {
            const int jl = ee ? jl1 : jl0;
            float gi = sum[0][ee] * 0.00390625f + bias_s[(0 + jl) * 128 + bb];
            float gf = sum[1][ee] * 0.00390625f + bias_s[(8 + jl) * 128 + bb];
            float gg = sum[2][ee] * 0.00390625f + bias_s[(16 + jl) * 128 + bb];
            float go = sum[3][ee] * 0.00390625f + bias_s[(24 + jl) * 128 + bb];
            if (t >= 364) {
                gi += fl * __ldcg(W_ih + (j0 + jl) * 60 + 32);
                gf += fl * __ldcg(W_ih + (1024 + j0 + jl) * 60 + 32);
                gg += fl * __ldcg(W_ih + (2048 + j0 + jl) * 60 + 32);
                go += fl * __ldcg(W_ih + (3072 + j0 + jl) * 60 + 32);
            }
            cst[ee] = sigm(gf) * cst[ee] + sigm(gi) * tanhf(gg);
            float hn = sigm(go) * tanhf(cst[ee]);
            if (t == 363) {
                const float te = temb_s[jl * 128 + bb];
                hn += te; cst[ee] += te;
            }
            hv[ee] = hn;
        }

        // store h
        {
            float h0, l0, h1, l1;
            split16(hv[0], h0, l0); split16(hv[1], h1, l1);
            const int addr = ((ktw * 8 + mt0 + emt) * 32 + g * 4 + tig) * 4 + regw + ehalf;
            g_hh[(t + 1) & 1][addr] = pk_h2(h0, h1);
            g_hl[(t + 1) & 1][addr] = pk_h2(l0, l1);
        }

        if (t >= 364) {
            float p = hv[0] * wh_s[jl0] + hv[1] * wh_s[jl1];
            p += __shfl_xor_sync(0xFFFFFFFFu, p, 1);
            p += __shfl_xor_sync(0xFFFFFFFFu, p, 2);
            if (tig == 0)
                g_part[(cta * 8 + (t - 364)) * BSZ + bb] = p;
        }

        // ---- grid barrier ----
        __syncthreads();
        if (tid == 0)
            asm volatile("red.release.gpu.global.add.u32 [%0], 1;"
                         :: "l"(g_cnt8 + (cta & 7) * 32) : "memory");
        if (tid < 8) {
            const unsigned target = 16u * (unsigned)(t + 1);
            unsigned v;
            do {
                asm volatile("ld.acquire.gpu.global.u32 %0, [%1];"
                             : "=r"(v) : "l"(g_cnt8 + tid * 32) : "memory");
                if (v < target) __nanosleep(32);
            } while (v < target);
        }
        __syncthreads();
    }
}

__global__ void out_kernel(const float* __restrict__ bh, float* __restrict__ out)
{
    const int idx = blockIdx.x * blockDim.x + threadIdx.x;
    if (idx >= BSZ * 8) return;
    const int b = idx >> 3, tf = idx & 7;
    float s = bh[0];
    #pragma unroll 4
    for (int c = 0; c < NCTA; ++c)
        s += g_part[(c * 8 + tf) * BSZ + b];
    out[idx] = s;
}

extern "C" void kernel_launch(void* const* d_in, const int* in_sizes, int n_in,
                              void* d_out, int out_size)
{
    const int smemb = SB_U32 * 4 + (4096 + 1024 + 32 + 4 * 3200) * 4;
    cudaFuncSetAttribute(lstm_main, cudaFuncAttributeMaxDynamicSharedMemorySize, smemb);
    s_emb_hm<<<128, 256>>>((const float*)d_in[2], (const float*)d_in[9],
                           (const float*)d_in[10], (const float*)d_in[11],
                           (const float*)d_in[12]);
    s_temb<<<128, 128>>>((const float*)d_in[13], (const float*)d_in[14]);
    s_biasx<<<404, 256>>>((const float*)d_in[4], (const float*)d_in[5],
                          (const float*)d_in[7], (const float*)d_in[8],
                          (const float*)d_in[0], (const float*)d_in[3],
                          (const float*)d_in[1]);
    lstm_main<<<NCTA, 512, smemb>>>((const float*)d_in[6], (const float*)d_in[5],
                                    (const float*)d_in[15], (const float*)d_in[1]);
    out_kernel<<<(BSZ * 8 + 255) / 256, 256>>>((const float*)d_in[16], (float*)d_out);
}